// round 5
// baseline (speedup 1.0000x reference)
#include <cuda_runtime.h>
#include <cstdint>

#define FULLMASK 0xffffffffu
#define L2E 1.4426950408889634f
#define MAXB 8192

static __device__ int g_perm[MAXB];

static __device__ __forceinline__ float ex2f_(float x) {
    float r; asm("ex2.approx.f32 %0, %1;" : "=f"(r) : "f"(x)); return r;
}
static __device__ __forceinline__ float rcpf_(float x) {
    float r; asm("rcp.approx.f32 %0, %1;" : "=f"(r) : "f"(x)); return r;
}
// sigmoid(x) = 1 - 1/(1+e^x) ; tanh(x) = 1 - 2/(1+e^{2x})
static __device__ __forceinline__ float sigm_(float x) {
    float u = ex2f_(L2E * x);
    return fmaf(-1.0f, rcpf_(1.0f + u), 1.0f);
}
static __device__ __forceinline__ float tanh_(float x) {
    float u = ex2f_(2.0f * L2E * x);
    return fmaf(-2.0f, rcpf_(1.0f + u), 1.0f);
}

// ---- packed f32x2 helpers (sm_103a) ----
static __device__ __forceinline__ uint64_t pk(float lo, float hi) {
    uint64_t r; asm("mov.b64 %0, {%1,%2};" : "=l"(r) : "f"(lo), "f"(hi)); return r;
}
static __device__ __forceinline__ uint64_t fma2(uint64_t a, uint64_t b, uint64_t c) {
    uint64_t d; asm("fma.rn.f32x2 %0, %1, %2, %3;" : "=l"(d) : "l"(a), "l"(b), "l"(c));
    return d;
}
static __device__ __forceinline__ uint64_t add2(uint64_t a, uint64_t b) {
    uint64_t d; asm("add.rn.f32x2 %0, %1, %2;" : "=l"(d) : "l"(a), "l"(b));
    return d;
}
static __device__ __forceinline__ float hadd2(uint64_t p) {
    float lo, hi; asm("mov.b64 {%0,%1}, %2;" : "=f"(lo), "=f"(hi) : "l"(p));
    return lo + hi;
}
static __device__ __forceinline__ void load8p(uint64_t* d, const float* p) {
    float4 a = *(const float4*)(p);
    float4 b = *(const float4*)(p + 4);
    d[0] = pk(a.x, a.y); d[1] = pk(a.z, a.w);
    d[2] = pk(b.x, b.y); d[3] = pk(b.z, b.w);
}
// broadcast h (one scalar per lane, unit r) to 4 packed pairs within 8-lane group
static __device__ __forceinline__ void bcast8(uint64_t* d, float h) {
#pragma unroll
    for (int k = 0; k < 4; k++) {
        float lo = __shfl_sync(FULLMASK, h, 2 * k,     8);
        float hi = __shfl_sync(FULLMASK, h, 2 * k + 1, 8);
        d[k] = pk(lo, hi);
    }
}

// one LSTM cell step for this lane's hidden unit.
// vp = input vector (4 pairs), hp = hidden vector (4 pairs), both group-replicated.
// wi/wh[gate][4]: this unit's gate rows. bp[gate] = pk(bias, 0).
// updates c, returns new h (scalar, this unit).
static __device__ __forceinline__ float lstm_unit(
    const uint64_t (&wi)[4][4], const uint64_t (&wh)[4][4],
    const uint64_t (&bp)[4], const uint64_t (&vp)[4], const uint64_t (&hp)[4],
    float& c)
{
    const uint64_t z = pk(0.0f, 0.0f);
    float a[4];
#pragma unroll
    for (int g = 0; g < 4; g++) {
        uint64_t A = fma2(wi[g][0], vp[0], bp[g]);
        uint64_t Bq = fma2(wi[g][1], vp[1], z);
        A  = fma2(wi[g][2], vp[2], A);
        Bq = fma2(wi[g][3], vp[3], Bq);
        A  = fma2(wh[g][0], hp[0], A);
        Bq = fma2(wh[g][1], hp[1], Bq);
        A  = fma2(wh[g][2], hp[2], A);
        Bq = fma2(wh[g][3], hp[3], Bq);
        a[g] = hadd2(add2(A, Bq));
    }
    float ig = sigm_(a[0]);
    float fg = sigm_(a[1]);
    float gg = tanh_(a[2]);
    float og = sigm_(a[3]);
    c = fmaf(fg, c, ig * gg);
    return og * tanh_(c);
}

// ---- rank-by-counting: perm[rank] = idx, descending length ----
__global__ void rank_kernel(const int* __restrict__ lengths, int B) {
    __shared__ int sl[4096];
    int tid = threadIdx.x;
    for (int j = tid; j < B; j += blockDim.x) sl[j] = lengths[j];
    __syncthreads();
    int idx = blockIdx.x * blockDim.x + tid;
    if (idx >= B) return;
    int L = sl[idx];
    int rank = 0;
    for (int j = 0; j < B; j++) {
        int lj = sl[j];
        rank += (lj > L) || (lj == L && j < idx);
    }
    g_perm[rank] = idx;
}

__global__ void __launch_bounds__(128, 1)
rnn_ac_kernel(const float* __restrict__ seq, const int* __restrict__ lengths,
              const float* __restrict__ Wih0, const float* __restrict__ Whh0,
              const float* __restrict__ bih0, const float* __restrict__ bhh0,
              const float* __restrict__ Wih1, const float* __restrict__ Whh1,
              const float* __restrict__ bih1, const float* __restrict__ bhh1,
              const float* __restrict__ Wl,  const float* __restrict__ bl,
              const float* __restrict__ Wv,  const float* __restrict__ bv,
              const float* __restrict__ Wa,  const float* __restrict__ ba,
              const float* __restrict__ log_std,
              float* __restrict__ out, int B, int S, int use_perm)
{
    const int warp = (blockIdx.x * blockDim.x + threadIdx.x) >> 5;
    const int lane = threadIdx.x & 31;
    const int grp  = lane >> 3;      // 4 sequences per warp
    const int r    = lane & 7;       // hidden unit owned by this lane
    const int nw   = (B + 3) >> 2;
    if (warp >= nw) return;
    int idx4 = warp * 4 + grp;
    if (idx4 >= B) idx4 = B - 1;
    const int b = use_perm ? g_perm[idx4] : idx4;

    // this unit's gate rows (i,f,g,o) for both layers, packed f32x2
    uint64_t wi0[4][4], wh0[4][4], wi1[4][4], wh1[4][4];
    uint64_t bp0[4], bp1[4];
#pragma unroll
    for (int g = 0; g < 4; g++) {
        load8p(wi0[g], Wih0 + (g * 8 + r) * 8);
        load8p(wh0[g], Whh0 + (g * 8 + r) * 8);
        load8p(wi1[g], Wih1 + (g * 8 + r) * 8);
        load8p(wh1[g], Whh1 + (g * 8 + r) * 8);
        bp0[g] = pk(bih0[g * 8 + r] + bhh0[g * 8 + r], 0.0f);
        bp1[g] = pk(bih1[g * 8 + r] + bhh1[g * 8 + r], 0.0f);
    }

    const int Lg = lengths[b];
    int maxL = Lg;
    maxL = max(maxL, __shfl_xor_sync(FULLMASK, maxL, 8));
    maxL = max(maxL, __shfl_xor_sync(FULLMASK, maxL, 16));

    const float* xbase = seq + (size_t)b * (size_t)S * 8;

    uint64_t h0p[4], h1p[4], xp[4];
#pragma unroll
    for (int k = 0; k < 4; k++) { h0p[k] = pk(0.f, 0.f); h1p[k] = pk(0.f, 0.f); }
    float c0 = 0.0f, c1 = 0.0f, h1snap = 0.0f;

    // prologue: layer0 step 0
    load8p(xp, xbase);
    {
        float h0 = lstm_unit(wi0, wh0, bp0, xp, h0p, c0);
        bcast8(h0p, h0);
    }
    load8p(xp, xbase + (size_t)min(1, Lg - 1) * 8);

    // iteration t: layer1 computes step t-1, layer0 computes step t.
    // layer0 past Lg computes garbage (clamped x) that never reaches outputs.
#pragma unroll 2
    for (int t = 1; t <= maxL; t++) {
        uint64_t xn[4];
        const float* xaddr = xbase + (size_t)min(t + 1, Lg - 1) * 8;
        load8p(xn, xaddr);
        asm volatile("prefetch.global.L2 [%0];"
                     :: "l"(xbase + (size_t)min(t + 5, Lg - 1) * 8));

        float h1 = lstm_unit(wi1, wh1, bp1, h0p, h1p, c1);
        h1snap = (t == Lg) ? h1 : h1snap;   // capture last valid layer1 output
        float h0 = lstm_unit(wi0, wh0, bp0, xp, h0p, c0);

        bcast8(h1p, h1);
        bcast8(h0p, h0);
#pragma unroll
        for (int k = 0; k < 4; k++) xp[k] = xn[k];
    }

    // re-broadcast the snapshotted final h1 within the group
    uint64_t hf[4];
    bcast8(hf, h1snap);

    // heads: feat = tanh(h1 @ Wl^T + bl) — computed redundantly per lane
    float feat[4];
#pragma unroll
    for (int j = 0; j < 4; j++) {
        uint64_t wlp[4];
        load8p(wlp, Wl + j * 8);
        uint64_t A  = fma2(wlp[0], hf[0], pk(bl[j], 0.0f));
        uint64_t Bq = fma2(wlp[1], hf[1], pk(0.f, 0.f));
        A  = fma2(wlp[2], hf[2], A);
        Bq = fma2(wlp[3], hf[3], Bq);
        feat[j] = tanh_(hadd2(add2(A, Bq)));
    }

    if (r == 0) {
        float v = bv[0];
#pragma unroll
        for (int j = 0; j < 4; j++) v = fmaf(Wv[j], feat[j], v);
        out[b] = v;                                   // value [B,1]
    }
    if (r < 4) {
        float m = ba[r];
#pragma unroll
        for (int j = 0; j < 4; j++) m = fmaf(Wa[r * 4 + j], feat[j], m);
        out[B + b * 4 + r] = m;                       // action_mean [B,4]
        float lsv = log_std[r];
        out[5 * B + b * 4 + r] = lsv;                 // action_log_std [B,4]
        out[9 * B + b * 4 + r] = ex2f_(lsv * L2E);    // action_std [B,4]
    }
}

extern "C" void kernel_launch(void* const* d_in, const int* in_sizes, int n_in,
                              void* d_out, int out_size)
{
    const float* seq     = (const float*)d_in[0];
    const int*   lengths = (const int*)d_in[1];
    const float* Wih0 = (const float*)d_in[2];
    const float* Whh0 = (const float*)d_in[3];
    const float* bih0 = (const float*)d_in[4];
    const float* bhh0 = (const float*)d_in[5];
    const float* Wih1 = (const float*)d_in[6];
    const float* Whh1 = (const float*)d_in[7];
    const float* bih1 = (const float*)d_in[8];
    const float* bhh1 = (const float*)d_in[9];
    const float* Wl = (const float*)d_in[10];
    const float* bl = (const float*)d_in[11];
    const float* Wv = (const float*)d_in[12];
    const float* bv = (const float*)d_in[13];
    const float* Wa = (const float*)d_in[14];
    const float* ba = (const float*)d_in[15];
    const float* ls = (const float*)d_in[16];
    float* out = (float*)d_out;

    int B = in_sizes[1];
    int S = in_sizes[0] / (B * 8);

    int use_perm = (B <= 4096) ? 1 : 0;
    if (use_perm) {
        int rthreads = 256;
        rank_kernel<<<(B + rthreads - 1) / rthreads, rthreads>>>(lengths, B);
    }

    int nw = (B + 3) / 4;                 // 4 sequences per warp
    int threads = 128;
    int grid = (nw * 32 + threads - 1) / threads;
    rnn_ac_kernel<<<grid, threads>>>(seq, lengths, Wih0, Whh0, bih0, bhh0,
                                     Wih1, Whh1, bih1, bhh1,
                                     Wl, bl, Wv, bv, Wa, ba, ls, out, B, S,
                                     use_perm);
}

// round 6
// speedup vs baseline: 1.7980x; 1.7980x over previous
#include <cuda_runtime.h>
#include <cstdint>

#define FULLMASK 0xffffffffu
#define L2E 1.4426950408889634f
#define MAXB 8192

static __device__ int g_perm[MAXB];

static __device__ __forceinline__ float ex2f_(float x) {
    float r; asm("ex2.approx.f32 %0, %1;" : "=f"(r) : "f"(x)); return r;
}
static __device__ __forceinline__ float rcpf_(float x) {
    float r; asm("rcp.approx.f32 %0, %1;" : "=f"(r) : "f"(x)); return r;
}
// sigmoid(x) = 1 - 1/(1+e^x) (kk=L2E,mm=1) ; tanh(x) = 1 - 2/(1+e^{2x}) (kk=2L2E,mm=2)
static __device__ __forceinline__ float gact(float x, float kk, float mm) {
    return fmaf(-mm, rcpf_(1.0f + ex2f_(kk * x)), 1.0f);
}
static __device__ __forceinline__ float tanh_(float x) {
    return fmaf(-2.0f, rcpf_(1.0f + ex2f_(2.0f * L2E * x)), 1.0f);
}

// ---- packed f32x2 helpers ----
static __device__ __forceinline__ uint64_t pk(float lo, float hi) {
    uint64_t r; asm("mov.b64 %0, {%1,%2};" : "=l"(r) : "f"(lo), "f"(hi)); return r;
}
static __device__ __forceinline__ void upk(uint64_t p, float& lo, float& hi) {
    asm("mov.b64 {%0,%1}, %2;" : "=f"(lo), "=f"(hi) : "l"(p));
}
static __device__ __forceinline__ float plo(uint64_t p) {
    float lo, hi; upk(p, lo, hi); return lo;
}
static __device__ __forceinline__ float phi(uint64_t p) {
    float lo, hi; upk(p, lo, hi); return hi;
}
static __device__ __forceinline__ uint64_t fma2(uint64_t a, uint64_t b, uint64_t c) {
    uint64_t d; asm("fma.rn.f32x2 %0, %1, %2, %3;" : "=l"(d) : "l"(a), "l"(b), "l"(c));
    return d;
}
static __device__ __forceinline__ uint64_t add2(uint64_t a, uint64_t b) {
    uint64_t d; asm("add.rn.f32x2 %0, %1, %2;" : "=l"(d) : "l"(a), "l"(b));
    return d;
}
static __device__ __forceinline__ uint64_t mul2(uint64_t a, uint64_t b) {
    uint64_t d; asm("mul.rn.f32x2 %0, %1, %2;" : "=l"(d) : "l"(a), "l"(b));
    return d;
}
static __device__ __forceinline__ uint64_t shfl64_down(uint64_t v, int d) {
    return (uint64_t)__shfl_down_sync(FULLMASK, (unsigned long long)v, d);
}
static __device__ __forceinline__ void load8f(float* d, const float* p) {
    float4 a = *(const float4*)(p);
    float4 b = *(const float4*)(p + 4);
    d[0] = a.x; d[1] = a.y; d[2] = a.z; d[3] = a.w;
    d[4] = b.x; d[5] = b.y; d[6] = b.z; d[7] = b.w;
}

// ---- rank-by-counting: perm[rank] = idx, descending length ----
__global__ void rank_kernel(const int* __restrict__ lengths, int B) {
    __shared__ int sl[4096];
    int tid = threadIdx.x;
    for (int j = tid; j < B; j += blockDim.x) sl[j] = lengths[j];
    __syncthreads();
    int idx = blockIdx.x * blockDim.x + tid;
    if (idx >= B) return;
    int L = sl[idx];
    int rank = 0;
    for (int j = 0; j < B; j++) {
        int lj = sl[j];
        rank += (lj > L) || (lj == L && j < idx);
    }
    g_perm[rank] = idx;
}

__global__ void __launch_bounds__(128, 1)
rnn_ac_kernel(const float* __restrict__ seq, const int* __restrict__ lengths,
              const float* __restrict__ Wih0, const float* __restrict__ Whh0,
              const float* __restrict__ bih0, const float* __restrict__ bhh0,
              const float* __restrict__ Wih1, const float* __restrict__ Whh1,
              const float* __restrict__ bih1, const float* __restrict__ bhh1,
              const float* __restrict__ Wl,  const float* __restrict__ bl,
              const float* __restrict__ Wv,  const float* __restrict__ bv,
              const float* __restrict__ Wa,  const float* __restrict__ ba,
              const float* __restrict__ log_std,
              float* __restrict__ out, int B, int S, int use_perm)
{
    __shared__ uint64_t hbuf[4][2][8];   // per-warp double-buffered h pairs

    const int warp = (blockIdx.x * blockDim.x + threadIdx.x) >> 5;
    const int lane = threadIdx.x & 31;   // gate index g (both layers)
    const int wI   = threadIdx.x >> 5;
    if (warp >= B) return;
    const int b = use_perm ? g_perm[warp] : warp;

    // paired weights: wA[k] = (Wih0[g,k], Wih1[g,k]); wB[k] = (Whh0[g,k], Whh1[g,k])
    uint64_t wA[8], wB[8];
#pragma unroll
    for (int k = 0; k < 8; k++) {
        wA[k] = pk(Wih0[lane * 8 + k], Wih1[lane * 8 + k]);
        wB[k] = pk(Whh0[lane * 8 + k], Whh1[lane * 8 + k]);
    }
    const uint64_t biasp = pk(bih0[lane] + bhh0[lane], bih1[lane] + bhh1[lane]);
    const uint64_t z64   = pk(0.0f, 0.0f);

    // gate type (same for both pair halves): lanes 16-23 = tanh gate
    const bool  isg = ((lane >> 3) == 2);
    const float kk  = isg ? 2.0f * L2E : L2E;
    const float mm  = isg ? 2.0f : 1.0f;

    const int Lg = lengths[b];
    const float* xbase = seq + (size_t)b * (size_t)S * 8;

    uint64_t q1[8], q2[8];     // q1 = (x_t, h0), q2 = (h0, h1)
    uint64_t cp = z64, hp = z64;

    float xr[8];
    load8f(xr, xbase);         // x_0

    // ---- peel iteration 0: layer0 step 0 (hi half computes garbage, zeroed) ----
    {
#pragma unroll
        for (int k = 0; k < 8; k++) { q1[k] = pk(xr[k], 0.0f); q2[k] = z64; }
        uint64_t A  = fma2(wA[0], q1[0], biasp);
        uint64_t Bq = fma2(wA[1], q1[1], z64);
#pragma unroll
        for (int k = 2; k < 8; k += 2) {
            A  = fma2(wA[k],     q1[k],     A);
            Bq = fma2(wA[k + 1], q1[k + 1], Bq);
        }
        uint64_t acc = add2(A, Bq);
        float alo, ahi; upk(acc, alo, ahi);
        uint64_t gp = pk(gact(alo, kk, mm), gact(ahi, kk, mm));
        uint64_t fp  = shfl64_down(gp, 8);
        uint64_t ggp = shfl64_down(gp, 16);
        uint64_t op  = shfl64_down(gp, 24);
        cp = fma2(fp, cp, mul2(gp, ggp));
        float clo, chi; upk(cp, clo, chi);
        hp = mul2(op, pk(tanh_(clo), tanh_(chi)));
        hp = pk(plo(hp), 0.0f);              // zero layer1 half
        cp = pk(plo(cp), 0.0f);
        if (lane < 8) hbuf[wI][0][lane] = hp;
        __syncwarp();
        const ulonglong2* src = (const ulonglong2*)&hbuf[wI][0][0];
#pragma unroll
        for (int k = 0; k < 4; k++) {
            ulonglong2 u = src[k];
            q2[2 * k] = u.x; q2[2 * k + 1] = u.y;
        }
        // x_1 and q1 for t=1
        load8f(xr, xbase + (size_t)min(1, Lg - 1) * 8);
#pragma unroll
        for (int k = 0; k < 8; k++) q1[k] = pk(xr[k], plo(q2[k]));
    }

    // ---- main loop: iteration t computes layer0 step t and layer1 step t-1 ----
    for (int t = 1; t <= Lg; t++) {
        // x_{t+1} for next iteration (clamped), issued early
        float xn[8];
        load8f(xn, xbase + (size_t)min(t + 1, Lg - 1) * 8);
        asm volatile("prefetch.global.L2 [%0];"
                     :: "l"(xbase + (size_t)min(t + 5, Lg - 1) * 8));

        // paired dot: (a0_g, a1_g)
        uint64_t A  = fma2(wA[0], q1[0], biasp);
        uint64_t Bq = fma2(wA[1], q1[1], z64);
#pragma unroll
        for (int k = 2; k < 8; k += 2) {
            A  = fma2(wA[k],     q1[k],     A);
            Bq = fma2(wA[k + 1], q1[k + 1], Bq);
        }
#pragma unroll
        for (int k = 0; k < 8; k += 2) {
            A  = fma2(wB[k],     q2[k],     A);
            Bq = fma2(wB[k + 1], q2[k + 1], Bq);
        }
        uint64_t acc = add2(A, Bq);

        float alo, ahi; upk(acc, alo, ahi);
        uint64_t gp = pk(gact(alo, kk, mm), gact(ahi, kk, mm));

        uint64_t fp  = shfl64_down(gp, 8);
        uint64_t ggp = shfl64_down(gp, 16);
        uint64_t op  = shfl64_down(gp, 24);

        cp = fma2(fp, cp, mul2(gp, ggp));          // (c0,c1) on lanes 0-7
        float clo, chi; upk(cp, clo, chi);
        hp = mul2(op, pk(tanh_(clo), tanh_(chi))); // (h0(t), h1(t-1))

        // broadcast h pair via smem (double-buffered)
        if (lane < 8) hbuf[wI][t & 1][lane] = hp;
        __syncwarp();
        const ulonglong2* src = (const ulonglong2*)&hbuf[wI][t & 1][0];
#pragma unroll
        for (int k = 0; k < 4; k++) {
            ulonglong2 u = src[k];
            q2[2 * k] = u.x; q2[2 * k + 1] = u.y;
        }
#pragma unroll
        for (int k = 0; k < 8; k++) q1[k] = pk(xn[k], plo(q2[k]));
    }

    // final h1 = hi half of hp (layer1 step Lg-1), valid on lanes 0-7
    float h1s = phi(hp);
    float h1a[8];
#pragma unroll
    for (int k = 0; k < 8; k++) h1a[k] = __shfl_sync(FULLMASK, h1s, k);

    // ---- heads ----
    float feat[4];
#pragma unroll
    for (int j = 0; j < 4; j++) {
        float a = bl[j];
#pragma unroll
        for (int k = 0; k < 8; k++) a = fmaf(Wl[j * 8 + k], h1a[k], a);
        feat[j] = tanh_(a);
    }

    if (lane == 0) {
        float v = bv[0];
#pragma unroll
        for (int j = 0; j < 4; j++) v = fmaf(Wv[j], feat[j], v);
        out[b] = v;                                   // value [B,1]
    }
    if (lane < 4) {
        float m = ba[lane];
#pragma unroll
        for (int j = 0; j < 4; j++) m = fmaf(Wa[lane * 4 + j], feat[j], m);
        out[B + b * 4 + lane] = m;                    // action_mean [B,4]
        float lsv = log_std[lane];
        out[5 * B + b * 4 + lane] = lsv;              // action_log_std [B,4]
        out[9 * B + b * 4 + lane] = ex2f_(lsv * L2E); // action_std [B,4]
    }
}

extern "C" void kernel_launch(void* const* d_in, const int* in_sizes, int n_in,
                              void* d_out, int out_size)
{
    const float* seq     = (const float*)d_in[0];
    const int*   lengths = (const int*)d_in[1];
    const float* Wih0 = (const float*)d_in[2];
    const float* Whh0 = (const float*)d_in[3];
    const float* bih0 = (const float*)d_in[4];
    const float* bhh0 = (const float*)d_in[5];
    const float* Wih1 = (const float*)d_in[6];
    const float* Whh1 = (const float*)d_in[7];
    const float* bih1 = (const float*)d_in[8];
    const float* bhh1 = (const float*)d_in[9];
    const float* Wl = (const float*)d_in[10];
    const float* bl = (const float*)d_in[11];
    const float* Wv = (const float*)d_in[12];
    const float* bv = (const float*)d_in[13];
    const float* Wa = (const float*)d_in[14];
    const float* ba = (const float*)d_in[15];
    const float* ls = (const float*)d_in[16];
    float* out = (float*)d_out;

    int B = in_sizes[1];
    int S = in_sizes[0] / (B * 8);

    int use_perm = (B <= 4096) ? 1 : 0;
    if (use_perm) {
        int rthreads = 256;
        rank_kernel<<<(B + rthreads - 1) / rthreads, rthreads>>>(lengths, B);
    }

    int threads = 128;                       // 4 warps/CTA, 1 sequence per warp
    int grid = (B * 32 + threads - 1) / threads;
    rnn_ac_kernel<<<grid, threads>>>(seq, lengths, Wih0, Whh0, bih0, bhh0,
                                     Wih1, Whh1, bih1, bhh1,
                                     Wl, bl, Wv, bv, Wa, ba, ls, out, B, S,
                                     use_perm);
}